// round 7
// baseline (speedup 1.0000x reference)
#include <cuda_runtime.h>
#include <cuda_bf16.h>

// Scratch (device globals — no allocation allowed)
__device__ float g_sub[256];
__device__ float g_gia[768];     // input-side gates for seed GRU
__device__ float g_r0[256];
__device__ float g_gi2[768];
__device__ float g_obj[1024 * 256];  // per-relation output table (R <= 1024)

__device__ __forceinline__ float sigmoidf(float x) {
    return 1.0f / (1.0f + __expf(-x));
}

__device__ __forceinline__ float dot4(float4 a, float4 b) {
    return fmaf(a.x, b.x, fmaf(a.y, b.y, fmaf(a.z, b.z, a.w * b.w)));
}

__device__ __forceinline__ float warp_reduce(float v) {
#pragma unroll
    for (int off = 16; off; off >>= 1) v += __shfl_xor_sync(0xffffffffu, v, off);
    return v;
}

__device__ __forceinline__ float warp_row_dot(const float* __restrict__ W_row,
                                              const float* __restrict__ x, int lane) {
    const float4* wp = reinterpret_cast<const float4*>(W_row);
    const float4* xp = reinterpret_cast<const float4*>(x);
    return warp_reduce(dot4(wp[lane], xp[lane]) + dot4(wp[lane + 32], xp[lane + 32]));
}

// K1: warps 0..255: sub[w] = tanh(mask . sub_W[w] + sub_b[w])
//     warps 256..1023: gia[w-256] = enc . W_ih[w-256] + b_ih[w-256]
// 128-thread blocks -> 256 blocks -> spans the whole chip.
__global__ void k_sub_gia(const float* __restrict__ mask, const float* __restrict__ sub_W,
                          const float* __restrict__ sub_b, const float* __restrict__ enc,
                          const float* __restrict__ W_ih, const float* __restrict__ b_ih) {
    int w = (blockIdx.x * blockDim.x + threadIdx.x) >> 5;
    int lane = threadIdx.x & 31;
    if (w < 256) {
        float acc = warp_row_dot(sub_W + (size_t)w * 256, mask, lane);
        if (lane == 0) g_sub[w] = tanhf(acc + sub_b[w]);
    } else if (w < 1024) {
        int j = w - 256;
        float acc = warp_row_dot(W_ih + (size_t)j * 256, enc, lane);
        if (lane == 0) g_gia[j] = acc + b_ih[j];
    }
}

// K2: one warp per d (256 warps): three W_hh row dots with sub -> gates -> r0[d]
__global__ void k_gha_r0(const float* __restrict__ W_hh, const float* __restrict__ b_hh) {
    int w = (blockIdx.x * blockDim.x + threadIdx.x) >> 5;
    int lane = threadIdx.x & 31;
    if (w >= 256) return;
    int d = w;
    const float4* xr = reinterpret_cast<const float4*>(g_sub);
    const float4* wr = reinterpret_cast<const float4*>(W_hh + (size_t)d * 256);
    const float4* wz = reinterpret_cast<const float4*>(W_hh + (size_t)(256 + d) * 256);
    const float4* wn = reinterpret_cast<const float4*>(W_hh + (size_t)(512 + d) * 256);
    float4 x0 = xr[lane], x1 = xr[lane + 32];
    float hr = warp_reduce(dot4(wr[lane], x0) + dot4(wr[lane + 32], x1));
    float hz = warp_reduce(dot4(wz[lane], x0) + dot4(wz[lane + 32], x1));
    float hn = warp_reduce(dot4(wn[lane], x0) + dot4(wn[lane + 32], x1));
    if (lane == 0) {
        hr += b_hh[d]; hz += b_hh[256 + d]; hn += b_hh[512 + d];
        float r = sigmoidf(g_gia[d] + hr);
        float z = sigmoidf(g_gia[256 + d] + hz);
        float n = tanhf(g_gia[512 + d] + r * hn);
        g_r0[d] = (1.0f - z) * n + z * g_sub[d];
    }
}

// K3: gi2[j] = r0 . W_ih[j] + b_ih[j]. 768 warps, 192 blocks.
__global__ void k_gi2(const float* __restrict__ W_ih, const float* __restrict__ b_ih) {
    int w = (blockIdx.x * blockDim.x + threadIdx.x) >> 5;
    int lane = threadIdx.x & 31;
    if (w >= 768) return;
    float acc = warp_row_dot(W_ih + (size_t)w * 256, g_r0, lane);
    if (lane == 0) g_gi2[w] = acc + b_ih[w];
}

// K4: per-relation table, RT=8 relations per block, float4 weight loads.
#define RT 8
__global__ void k_reltable(const float* __restrict__ rel_table,
                           const float* __restrict__ W_hh, const float* __restrict__ b_hh,
                           const float* __restrict__ obj_W, const float* __restrict__ obj_b,
                           int R) {
    __shared__ float srel[RT][256];
    int d = threadIdx.x;
    int rbase = blockIdx.x * RT;

#pragma unroll
    for (int ri = 0; ri < RT; ri++) {
        int r = rbase + ri;
        srel[ri][d] = (r < R) ? rel_table[(size_t)r * 256 + d] : 0.0f;
    }
    __syncthreads();

    float ar[RT], az[RT], an[RT];
    {
        float br = b_hh[d], bz = b_hh[256 + d], bn = b_hh[512 + d];
#pragma unroll
        for (int ri = 0; ri < RT; ri++) { ar[ri] = br; az[ri] = bz; an[ri] = bn; }
    }

    const float4* wr4 = reinterpret_cast<const float4*>(W_hh + (size_t)d * 256);
    const float4* wz4 = reinterpret_cast<const float4*>(W_hh + (size_t)(256 + d) * 256);
    const float4* wn4 = reinterpret_cast<const float4*>(W_hh + (size_t)(512 + d) * 256);
#pragma unroll 2
    for (int k4 = 0; k4 < 64; k4++) {
        float4 vr = wr4[k4], vz = wz4[k4], vn = wn4[k4];
#pragma unroll
        for (int ri = 0; ri < RT; ri++) {
            float4 h = *reinterpret_cast<const float4*>(&srel[ri][k4 * 4]);
            ar[ri] = fmaf(vr.x, h.x, fmaf(vr.y, h.y, fmaf(vr.z, h.z, fmaf(vr.w, h.w, ar[ri]))));
            az[ri] = fmaf(vz.x, h.x, fmaf(vz.y, h.y, fmaf(vz.z, h.z, fmaf(vz.w, h.w, az[ri]))));
            an[ri] = fmaf(vn.x, h.x, fmaf(vn.y, h.y, fmaf(vn.z, h.z, fmaf(vn.w, h.w, an[ri]))));
        }
    }

    float gr = g_gi2[d], gz = g_gi2[256 + d], gn = g_gi2[512 + d];
    float rj[RT];
#pragma unroll
    for (int ri = 0; ri < RT; ri++) {
        float r = sigmoidf(gr + ar[ri]);
        float z = sigmoidf(gz + az[ri]);
        float n = tanhf(gn + r * an[ri]);
        rj[ri] = (1.0f - z) * n + z * srel[ri][d];
    }
    __syncthreads();
#pragma unroll
    for (int ri = 0; ri < RT; ri++) srel[ri][d] = rj[ri];
    __syncthreads();

    float ao[RT];
    {
        float bo = obj_b[d];
#pragma unroll
        for (int ri = 0; ri < RT; ri++) ao[ri] = bo;
    }
    const float4* wo4 = reinterpret_cast<const float4*>(obj_W + (size_t)d * 256);
#pragma unroll 2
    for (int k4 = 0; k4 < 64; k4++) {
        float4 v = wo4[k4];
#pragma unroll
        for (int ri = 0; ri < RT; ri++) {
            float4 h = *reinterpret_cast<const float4*>(&srel[ri][k4 * 4]);
            ao[ri] = fmaf(v.x, h.x, fmaf(v.y, h.y, fmaf(v.z, h.z, fmaf(v.w, h.w, ao[ri]))));
        }
    }
#pragma unroll
    for (int ri = 0; ri < RT; ri++) {
        int r = rbase + ri;
        if (r < R) g_obj[(size_t)r * 256 + d] = tanhf(ao[ri]);
    }
}

// Entity-gather edges (state==1): independent of the GRU chain. Low-priority side stream.
__global__ void k_edges_entity(const float* __restrict__ entity_table,
                               const int* __restrict__ tail_ids,
                               const int* __restrict__ tails_state,
                               const int* __restrict__ origin_ids,
                               float* __restrict__ out, int E) {
    long long t = (long long)blockIdx.x * blockDim.x + threadIdx.x;
    int e = (int)(t >> 6);
    int j = (int)(t & 63);
    if (e >= E) return;
    if (tails_state[e] != 1) return;          // warp-uniform
    long long org = origin_ids[e];
    float4 val = reinterpret_cast<const float4*>(entity_table)[org * 64 + j];
    long long row = tail_ids[e];
    reinterpret_cast<float4*>(out)[row * 64 + j] = val;
}

// Obj-table edges (state==0) + seed row (e == E). Depends on g_obj / g_sub.
__global__ void k_edges_obj(const int* __restrict__ rel_ids,
                            const int* __restrict__ tail_ids,
                            const int* __restrict__ tails_state,
                            float* __restrict__ out, int E) {
    long long t = (long long)blockIdx.x * blockDim.x + threadIdx.x;
    int e = (int)(t >> 6);
    int j = (int)(t & 63);
    if (e > E) return;
    if (e == E) {  // seed row: out[E] = sub
        reinterpret_cast<float4*>(out)[(long long)E * 64 + j] =
            reinterpret_cast<const float4*>(g_sub)[j];
        return;
    }
    if (tails_state[e] != 0) return;          // warp-uniform
    long long r = rel_ids[e];
    float4 val = reinterpret_cast<const float4*>(g_obj)[r * 64 + j];
    long long row = tail_ids[e];
    reinterpret_cast<float4*>(out)[row * 64 + j] = val;
}

static cudaStream_t g_side = nullptr;
static cudaEvent_t g_ev_fork = nullptr;
static cudaEvent_t g_ev_join = nullptr;

extern "C" void kernel_launch(void* const* d_in, const int* in_sizes, int n_in,
                              void* d_out, int out_size) {
    const float* enc        = (const float*)d_in[0];
    const float* mask       = (const float*)d_in[1];
    const float* entity     = (const float*)d_in[2];
    const float* rel_table  = (const float*)d_in[3];
    const float* W_ih       = (const float*)d_in[4];
    const float* W_hh       = (const float*)d_in[5];
    const float* b_ih       = (const float*)d_in[6];
    const float* b_hh       = (const float*)d_in[7];
    const float* sub_W      = (const float*)d_in[8];
    const float* sub_b      = (const float*)d_in[9];
    const float* obj_W      = (const float*)d_in[10];
    const float* obj_b      = (const float*)d_in[11];
    const int*   rel_ids    = (const int*)d_in[12];
    const int*   tail_ids   = (const int*)d_in[13];
    const int*   tails_state= (const int*)d_in[14];
    const int*   origin_ids = (const int*)d_in[15];

    float* out = (float*)d_out;
    int E = in_sizes[12];           // edge count; seed == E by construction
    int R = in_sizes[3] / 256;      // relation vocab

    if (g_side == nullptr) {        // host-side objects only; created once, outside capture
        int leastPrio = 0, greatestPrio = 0;
        cudaDeviceGetStreamPriorityRange(&leastPrio, &greatestPrio);
        // leastPrio = numerically largest = LOWEST priority: entity blocks yield to chain
        cudaStreamCreateWithPriority(&g_side, cudaStreamNonBlocking, leastPrio);
        cudaEventCreateWithFlags(&g_ev_fork, cudaEventDisableTiming);
        cudaEventCreateWithFlags(&g_ev_join, cudaEventDisableTiming);
    }

    // ---- dependent chain on the main (high-priority) stream, enqueued FIRST ----
    k_sub_gia<<<256, 128>>>(mask, sub_W, sub_b, enc, W_ih, b_ih);  // 1024 warps, 256 SM-wide blocks
    k_gha_r0<<<64, 128>>>(W_hh, b_hh);                             // 256 warps
    k_gi2<<<192, 128>>>(W_ih, b_ih);                               // 768 warps

    // ---- fork: entity-gather edges fill idle SMs at LOW priority ----
    cudaEventRecord(g_ev_fork, 0);
    cudaStreamWaitEvent(g_side, g_ev_fork, 0);
    {
        long long total = (long long)E * 64;
        int blocks = (int)((total + 255) / 256);
        k_edges_entity<<<blocks, 256, 0, g_side>>>(entity, tail_ids, tails_state,
                                                   origin_ids, out, E);
    }
    cudaEventRecord(g_ev_join, g_side);

    k_reltable<<<(R + RT - 1) / RT, 256>>>(rel_table, W_hh, b_hh, obj_W, obj_b, R);
    {
        long long total = (long long)(E + 1) * 64;
        int blocks = (int)((total + 255) / 256);
        k_edges_obj<<<blocks, 256>>>(rel_ids, tail_ids, tails_state, out, E);
    }

    // ---- join side stream back before returning ----
    cudaStreamWaitEvent(0, g_ev_join, 0);
}

// round 11
// speedup vs baseline: 1.9895x; 1.9895x over previous
#include <cuda_runtime.h>
#include <cuda_bf16.h>

// Scratch (device globals — no allocation allowed)
__device__ float g_sub[256];
__device__ float g_gia[768];     // input-side gates for seed GRU
__device__ float g_r0[256];
__device__ float g_gi2[768];
__device__ float g_obj[1024 * 256];  // per-relation output table (R <= 1024)

__device__ __forceinline__ float sigmoidf(float x) {
    return 1.0f / (1.0f + __expf(-x));
}

__device__ __forceinline__ float dot4(float4 a, float4 b) {
    return fmaf(a.x, b.x, fmaf(a.y, b.y, fmaf(a.z, b.z, a.w * b.w)));
}

__device__ __forceinline__ float warp_reduce(float v) {
#pragma unroll
    for (int off = 16; off; off >>= 1) v += __shfl_xor_sync(0xffffffffu, v, off);
    return v;
}

__device__ __forceinline__ float warp_row_dot(const float* __restrict__ W_row,
                                              const float* __restrict__ x, int lane) {
    const float4* wp = reinterpret_cast<const float4*>(W_row);
    const float4* xp = reinterpret_cast<const float4*>(x);
    return warp_reduce(dot4(wp[lane], xp[lane]) + dot4(wp[lane + 32], xp[lane + 32]));
}

// K1: warps 0..255: sub[w] = tanh(mask . sub_W[w] + sub_b[w])
//     warps 256..1023: gia[w-256] = enc . W_ih[w-256] + b_ih[w-256]
__global__ void k_sub_gia(const float* __restrict__ mask, const float* __restrict__ sub_W,
                          const float* __restrict__ sub_b, const float* __restrict__ enc,
                          const float* __restrict__ W_ih, const float* __restrict__ b_ih) {
    int w = (blockIdx.x * blockDim.x + threadIdx.x) >> 5;
    int lane = threadIdx.x & 31;
    if (w < 256) {
        float acc = warp_row_dot(sub_W + (size_t)w * 256, mask, lane);
        if (lane == 0) g_sub[w] = tanhf(acc + sub_b[w]);
    } else if (w < 1024) {
        int j = w - 256;
        float acc = warp_row_dot(W_ih + (size_t)j * 256, enc, lane);
        if (lane == 0) g_gia[j] = acc + b_ih[j];
    }
}

// K2: one warp per d (256 warps): three W_hh row dots with sub -> gates -> r0[d]
__global__ void k_gha_r0(const float* __restrict__ W_hh, const float* __restrict__ b_hh) {
    int w = (blockIdx.x * blockDim.x + threadIdx.x) >> 5;
    int lane = threadIdx.x & 31;
    if (w >= 256) return;
    int d = w;
    const float4* xr = reinterpret_cast<const float4*>(g_sub);
    const float4* wr = reinterpret_cast<const float4*>(W_hh + (size_t)d * 256);
    const float4* wz = reinterpret_cast<const float4*>(W_hh + (size_t)(256 + d) * 256);
    const float4* wn = reinterpret_cast<const float4*>(W_hh + (size_t)(512 + d) * 256);
    float4 x0 = xr[lane], x1 = xr[lane + 32];
    float hr = warp_reduce(dot4(wr[lane], x0) + dot4(wr[lane + 32], x1));
    float hz = warp_reduce(dot4(wz[lane], x0) + dot4(wz[lane + 32], x1));
    float hn = warp_reduce(dot4(wn[lane], x0) + dot4(wn[lane + 32], x1));
    if (lane == 0) {
        hr += b_hh[d]; hz += b_hh[256 + d]; hn += b_hh[512 + d];
        float r = sigmoidf(g_gia[d] + hr);
        float z = sigmoidf(g_gia[256 + d] + hz);
        float n = tanhf(g_gia[512 + d] + r * hn);
        g_r0[d] = (1.0f - z) * n + z * g_sub[d];
    }
}

// K3: gi2[j] = r0 . W_ih[j] + b_ih[j]. 768 warps, 192 blocks.
__global__ void k_gi2(const float* __restrict__ W_ih, const float* __restrict__ b_ih) {
    int w = (blockIdx.x * blockDim.x + threadIdx.x) >> 5;
    int lane = threadIdx.x & 31;
    if (w >= 768) return;
    float acc = warp_row_dot(W_ih + (size_t)w * 256, g_r0, lane);
    if (lane == 0) g_gi2[w] = acc + b_ih[w];
}

// K4: per-relation table, RT=8 relations per block, float4 weight loads.
#define RT 8
__global__ void k_reltable(const float* __restrict__ rel_table,
                           const float* __restrict__ W_hh, const float* __restrict__ b_hh,
                           const float* __restrict__ obj_W, const float* __restrict__ obj_b,
                           int R) {
    __shared__ float srel[RT][256];
    int d = threadIdx.x;
    int rbase = blockIdx.x * RT;

#pragma unroll
    for (int ri = 0; ri < RT; ri++) {
        int r = rbase + ri;
        srel[ri][d] = (r < R) ? rel_table[(size_t)r * 256 + d] : 0.0f;
    }
    __syncthreads();

    float ar[RT], az[RT], an[RT];
    {
        float br = b_hh[d], bz = b_hh[256 + d], bn = b_hh[512 + d];
#pragma unroll
        for (int ri = 0; ri < RT; ri++) { ar[ri] = br; az[ri] = bz; an[ri] = bn; }
    }

    const float4* wr4 = reinterpret_cast<const float4*>(W_hh + (size_t)d * 256);
    const float4* wz4 = reinterpret_cast<const float4*>(W_hh + (size_t)(256 + d) * 256);
    const float4* wn4 = reinterpret_cast<const float4*>(W_hh + (size_t)(512 + d) * 256);
#pragma unroll 2
    for (int k4 = 0; k4 < 64; k4++) {
        float4 vr = wr4[k4], vz = wz4[k4], vn = wn4[k4];
#pragma unroll
        for (int ri = 0; ri < RT; ri++) {
            float4 h = *reinterpret_cast<const float4*>(&srel[ri][k4 * 4]);
            ar[ri] = fmaf(vr.x, h.x, fmaf(vr.y, h.y, fmaf(vr.z, h.z, fmaf(vr.w, h.w, ar[ri]))));
            az[ri] = fmaf(vz.x, h.x, fmaf(vz.y, h.y, fmaf(vz.z, h.z, fmaf(vz.w, h.w, az[ri]))));
            an[ri] = fmaf(vn.x, h.x, fmaf(vn.y, h.y, fmaf(vn.z, h.z, fmaf(vn.w, h.w, an[ri]))));
        }
    }

    float gr = g_gi2[d], gz = g_gi2[256 + d], gn = g_gi2[512 + d];
    float rj[RT];
#pragma unroll
    for (int ri = 0; ri < RT; ri++) {
        float r = sigmoidf(gr + ar[ri]);
        float z = sigmoidf(gz + az[ri]);
        float n = tanhf(gn + r * an[ri]);
        rj[ri] = (1.0f - z) * n + z * srel[ri][d];
    }
    __syncthreads();
#pragma unroll
    for (int ri = 0; ri < RT; ri++) srel[ri][d] = rj[ri];
    __syncthreads();

    float ao[RT];
    {
        float bo = obj_b[d];
#pragma unroll
        for (int ri = 0; ri < RT; ri++) ao[ri] = bo;
    }
    const float4* wo4 = reinterpret_cast<const float4*>(obj_W + (size_t)d * 256);
#pragma unroll 2
    for (int k4 = 0; k4 < 64; k4++) {
        float4 v = wo4[k4];
#pragma unroll
        for (int ri = 0; ri < RT; ri++) {
            float4 h = *reinterpret_cast<const float4*>(&srel[ri][k4 * 4]);
            ao[ri] = fmaf(v.x, h.x, fmaf(v.y, h.y, fmaf(v.z, h.z, fmaf(v.w, h.w, ao[ri]))));
        }
    }
#pragma unroll
    for (int ri = 0; ri < RT; ri++) {
        int r = rbase + ri;
        if (r < R) g_obj[(size_t)r * 256 + d] = tanhf(ao[ri]);
    }
}

// K5: edge scatter. One warp per output row, 2 edges per warp (EPW=2).
// Each lane moves 2 x float4 per edge; handles st==0 (obj table), st==1 (entity
// gather) and the seed row (e == E) in a single pass.
#define EPW 2
__global__ void k_edges(const float* __restrict__ entity_table,
                        const int* __restrict__ rel_ids,
                        const int* __restrict__ tail_ids,
                        const int* __restrict__ tails_state,
                        const int* __restrict__ origin_ids,
                        float* __restrict__ out, int E) {
    int w = (blockIdx.x * blockDim.x + threadIdx.x) >> 5;
    int lane = threadIdx.x & 31;
    int e0 = w * EPW;
    if (e0 > E) return;

    float4 v0[EPW], v1[EPW];
    long long row[EPW];
    int cnt = 0;
#pragma unroll
    for (int k = 0; k < EPW; k++) {
        int e = e0 + k;
        if (e > E) break;
        cnt++;
        if (e == E) {               // seed row: out[E] = sub
            const float4* s = reinterpret_cast<const float4*>(g_sub);
            row[k] = E;
            v0[k] = s[lane];
            v1[k] = s[lane + 32];
        } else {
            int st = tails_state[e];            // warp-uniform broadcasts
            row[k] = tail_ids[e];
            if (st == 1) {
                const float4* s = reinterpret_cast<const float4*>(entity_table)
                                  + (long long)origin_ids[e] * 64;
                v0[k] = __ldcs(s + lane);       // streaming: no reuse
                v1[k] = __ldcs(s + lane + 32);
            } else {
                const float4* s = reinterpret_cast<const float4*>(g_obj)
                                  + (long long)rel_ids[e] * 64;
                v0[k] = __ldg(s + lane);        // cached: heavy L2 reuse (R=1000 rows)
                v1[k] = __ldg(s + lane + 32);
            }
        }
    }
#pragma unroll
    for (int k = 0; k < EPW; k++) {
        if (k >= cnt) break;
        float4* o = reinterpret_cast<float4*>(out) + row[k] * 64;
        __stcs(o + lane, v0[k]);                // streaming stores: don't pollute L2
        __stcs(o + lane + 32, v1[k]);
    }
}

extern "C" void kernel_launch(void* const* d_in, const int* in_sizes, int n_in,
                              void* d_out, int out_size) {
    const float* enc        = (const float*)d_in[0];
    const float* mask       = (const float*)d_in[1];
    const float* entity     = (const float*)d_in[2];
    const float* rel_table  = (const float*)d_in[3];
    const float* W_ih       = (const float*)d_in[4];
    const float* W_hh       = (const float*)d_in[5];
    const float* b_ih       = (const float*)d_in[6];
    const float* b_hh       = (const float*)d_in[7];
    const float* sub_W      = (const float*)d_in[8];
    const float* sub_b      = (const float*)d_in[9];
    const float* obj_W      = (const float*)d_in[10];
    const float* obj_b      = (const float*)d_in[11];
    const int*   rel_ids    = (const int*)d_in[12];
    const int*   tail_ids   = (const int*)d_in[13];
    const int*   tails_state= (const int*)d_in[14];
    const int*   origin_ids = (const int*)d_in[15];

    float* out = (float*)d_out;
    int E = in_sizes[12];           // edge count; seed == E by construction
    int R = in_sizes[3] / 256;      // relation vocab

    // Single stream, 5 kernels; chain grids span the whole chip.
    k_sub_gia<<<256, 128>>>(mask, sub_W, sub_b, enc, W_ih, b_ih);   // 1024 warps
    k_gha_r0<<<64, 128>>>(W_hh, b_hh);                              // 256 warps
    k_gi2<<<192, 128>>>(W_ih, b_ih);                                // 768 warps
    k_reltable<<<(R + RT - 1) / RT, 256>>>(rel_table, W_hh, b_hh, obj_W, obj_b, R);

    int rows = E + 1;                                   // E edges + seed row
    int warps = (rows + EPW - 1) / EPW;
    int blocks = (warps + 7) / 8;                       // 8 warps per 256-thread block
    k_edges<<<blocks, 256>>>(entity, rel_ids, tail_ids, tails_state, origin_ids, out, E);
}